// round 5
// baseline (speedup 1.0000x reference)
#include <cuda_runtime.h>
#include <cfloat>
#include <math.h>

#define BB   32
#define CC   256
#define GG   4
#define CG   64
#define HH   56
#define WW   56
#define OH   28
#define OW   28
#define HWp  (HH*WW)      // 3136
#define OHWp (OH*OW)      // 784
#define CNT  (BB*OHWp)    // 25088
#define BN_EPS 1e-5

// ---------------- scratch (device globals; no allocation allowed) ----------------
__device__ __align__(32) unsigned long long g_bits1[BB*GG*HWp]; // packed sign(x): [n][g][p]
__device__ unsigned g_bits2u[BB*8*OHWp];                        // packed sign(x1): [n][chunk32][p]
__device__ unsigned long long g_w1b[CC*9];                      // packed sign(w1): [oc][tap]
__device__ unsigned long long g_w2b[CC*4];                      // packed sign(w2): [oc][word]
__device__ short g_y1[BB*CC*OHWp];                              // conv1 raw ints
__device__ short g_y2[BB*CC*OHWp];                              // conv2 raw ints
__device__ float g_mp[BB*CC*OHWp];                              // maxpool shortcut
__device__ float g_x1[BB*CC*OHWp];                              // stage-1 output
__device__ long long g_sum1[CC], g_sq1[CC], g_sum2[CC], g_sq2[CC];
__device__ float g_scale1[CC], g_bias1[CC], g_scale2[CC], g_bias2[CC];

// ---------------- kernels ----------------

// Prolog: block = (n, g, row-half). Phase A packs sign(x) bit-planes for 28 input rows;
// phase B computes 3x3 s2 maxpool for the matching 14 output rows (x re-read is L2-hot).
__global__ void k_prolog(const float* __restrict__ x) {
    int b = blockIdx.x;                 // 32*4*2 = 256
    int half = b & 1, g = (b >> 1) & 3, n = b >> 3;
    int tid = threadIdx.x;
    const float* xg = x + ((size_t)(n*CC + g*CG)) * HWp;

    // ---- Phase A: pack. 1568 pixels -> 392 float4 units ----
    for (int u = tid; u < 392; u += 256) {
        int p = half * 1568 + u * 4;
        const float* xp = xg + p;
        unsigned long long m0=0, m1=0, m2=0, m3=0;
#pragma unroll 16
        for (int c = 0; c < CG; c++) {
            float4 v = *(const float4*)(xp + (size_t)c * HWp);
            unsigned long long bt = 1ull << c;
            if (v.x > 0.f) m0 |= bt;
            if (v.y > 0.f) m1 |= bt;
            if (v.z > 0.f) m2 |= bt;
            if (v.w > 0.f) m3 |= bt;
        }
        unsigned long long* o = g_bits1 + ((size_t)(n*GG + g)) * HWp + p;
        ulonglong2 a; a.x = m0; a.y = m1;
        ulonglong2 b2; b2.x = m2; b2.y = m3;
        *(ulonglong2*)o       = a;
        *(ulonglong2*)(o + 2) = b2;
    }

    // ---- Phase B: maxpool. warp-unit = (c, output row); lane = output col ----
    int wid = tid >> 5, lane = tid & 31;
    for (int u = wid; u < CG * 14; u += 8) {
        int c = u / 14, ohl = u - (u / 14) * 14;
        int oh = half * 14 + ohl;
        const float* xc = xg + (size_t)c * HWp;
        float a = -FLT_MAX, bmax = -FLT_MAX;
        if (lane < OW) {
            int ih0 = 2 * oh - 1;
#pragma unroll
            for (int r = 0; r < 3; r++) {
                int ih = ih0 + r;
                if (ih >= 0) {          // ih <= 55 always
                    float2 f = *(const float2*)(xc + ih * WW + 2 * lane);
                    a = fmaxf(a, fmaxf(f.x, f.y));
                    bmax = fmaxf(bmax, f.y);
                }
            }
        }
        float left = __shfl_up_sync(0xffffffffu, bmax, 1);
        float m = (lane == 0) ? a : fmaxf(a, left);
        if (lane < OW)
            g_mp[((size_t)(n*CC + g*CG + c)) * OHWp + oh * OW + lane] = m;
    }
}

// Pack weight sign bits + zero the stats accumulators (runs before convs each replay).
__global__ void k_pack_w(const float* __restrict__ w1, const float* __restrict__ w2) {
    int tid = blockIdx.x * blockDim.x + threadIdx.x;
    if (tid < CC * 9) {
        int oc = tid / 9, t = tid % 9;
        unsigned long long m = 0;
        for (int k = 0; k < CG; k++)
            if (w1[(size_t)(oc * CG + k) * 9 + t] > 0.f) m |= 1ull << k;
        g_w1b[tid] = m;
    } else if (tid < CC * 9 + CC * 4) {
        int r = tid - CC * 9;
        int oc = r / 4, j = r % 4;
        unsigned long long m = 0;
        for (int k = 0; k < 64; k++)
            if (w2[(size_t)oc * CC + j * 64 + k] > 0.f) m |= 1ull << k;
        g_w2b[r] = m;
    } else if (tid < CC * 9 + CC * 4 + 4 * CC) {
        int r = tid - (CC * 9 + CC * 4);
        int arr = r >> 8, c = r & 255;
        if      (arr == 0) g_sum1[c] = 0;
        else if (arr == 1) g_sq1[c]  = 0;
        else if (arr == 2) g_sum2[c] = 0;
        else               g_sq2[c]  = 0;
    }
}

__device__ __forceinline__ int warp_red(int v) {
#pragma unroll
    for (int o = 16; o; o >>= 1) v += __shfl_down_sync(0xffffffffu, v, o);
    return v;
}

// Reduce 16 per-thread (sum,sq) pairs across the block and atomically add to globals.
__device__ __forceinline__ void commit_stats16(int* asum, int* asq, int oc0,
                                               long long* gsum, long long* gsq) {
    __shared__ int sred[8][32];
    int lane = threadIdx.x & 31, wid = threadIdx.x >> 5;
#pragma unroll
    for (int oc = 0; oc < 16; oc++) {
        int s = warp_red(asum[oc]);
        int q = warp_red(asq[oc]);
        if (lane == 0) { sred[wid][oc] = s; sred[wid][16 + oc] = q; }
    }
    __syncthreads();
    if (threadIdx.x < 32) {
        int v = 0;
#pragma unroll
        for (int w = 0; w < 8; w++) v += sred[w][threadIdx.x];
        if (threadIdx.x < 16)
            atomicAdd((unsigned long long*)&gsum[oc0 + threadIdx.x], (unsigned long long)(long long)v);
        else
            atomicAdd((unsigned long long*)&gsq[oc0 + threadIdx.x - 16], (unsigned long long)(long long)v);
    }
}

// Grouped 3x3 s2 binary conv + fused BN1 stats. Block = (n, g, oc-tile of 16).
__global__ void k_conv1() {
    int b = blockIdx.x;                 // 512
    int octile = b & 3;
    int g = (b >> 2) & 3;
    int n = b >> 4;
    __shared__ unsigned long long sp[HWp];
    __shared__ unsigned long long sw[16][9];
    const unsigned long long* bp = g_bits1 + (size_t)(n*GG + g) * HWp;
    for (int i = threadIdx.x; i < HWp; i += 256) sp[i] = bp[i];
    if (threadIdx.x < 144) {
        int oc = threadIdx.x / 9, t = threadIdx.x % 9;
        sw[oc][t] = g_w1b[(size_t)(g*CG + octile*16 + oc) * 9 + t];
    }
    __syncthreads();
    int oc0 = g*CG + octile*16;
    short* yp = g_y1 + ((size_t)n*CC + oc0) * OHWp;
    int asum[16], asq[16];
#pragma unroll
    for (int i = 0; i < 16; i++) { asum[i] = 0; asq[i] = 0; }

    for (int p = threadIdx.x; p < OHWp; p += 256) {
        int oh = p / OW, ow = p - oh * OW;
        int ih0 = 2*oh - 1, iw0 = 2*ow - 1;
        unsigned long long a[9];
        if (oh > 0 && ow > 0) {
            const unsigned long long* r = sp + ih0 * WW + iw0;
            a[0]=r[0];    a[1]=r[1];      a[2]=r[2];
            a[3]=r[WW];   a[4]=r[WW+1];   a[5]=r[WW+2];
            a[6]=r[2*WW]; a[7]=r[2*WW+1]; a[8]=r[2*WW+2];
#pragma unroll
            for (int oc = 0; oc < 16; oc++) {
                int s = 0;
#pragma unroll
                for (int t = 0; t < 9; t++) s += __popcll(a[t] ^ sw[oc][t]);
                int val = 576 - 2*s;
                yp[(size_t)oc*OHWp + p] = (short)val;
                asum[oc] += val; asq[oc] += val * val;
            }
        } else {
            bool vld[9]; int nv = 0;
#pragma unroll
            for (int t = 0; t < 9; t++) {
                int ih = ih0 + t/3, iw = iw0 + t%3;
                bool v = ((unsigned)ih < HH) & ((unsigned)iw < WW);
                vld[t] = v;
                a[t] = v ? sp[ih*WW + iw] : 0ull;
                nv += v;
            }
#pragma unroll
            for (int oc = 0; oc < 16; oc++) {
                int s = 0;
#pragma unroll
                for (int t = 0; t < 9; t++) if (vld[t]) s += __popcll(a[t] ^ sw[oc][t]);
                int val = nv*64 - 2*s;
                yp[(size_t)oc*OHWp + p] = (short)val;
                asum[oc] += val; asq[oc] += val * val;
            }
        }
    }
    commit_stats16(asum, asq, oc0, g_sum1, g_sq1);
}

// BN scale/bias from exact integer stats. One block, 256 threads.
__global__ void k_sb(int which, const float* __restrict__ gamma, const float* __restrict__ beta) {
    int c = threadIdx.x;
    long long ts = which ? g_sum2[c] : g_sum1[c];
    long long tq = which ? g_sq2[c]  : g_sq1[c];
    double mu  = (double)ts / CNT;
    double var = (double)tq / CNT - mu * mu;
    double sc  = (double)gamma[c] / sqrt(var + BN_EPS);
    float scale = (float)sc;
    float bias  = (float)((double)beta[c] - mu * sc);
    if (which) { g_scale2[c] = scale; g_bias2[c] = bias; }
    else       { g_scale1[c] = scale; g_bias1[c] = bias; }
}

// x1 = bn1(y1) + mp; pack sign(x1). Pure streaming, all arrays same layout.
__global__ void k_apply1() {
    __shared__ float ssc[CC], sbi[CC];
    int tid = threadIdx.x;
    if (tid < CC) { ssc[tid] = g_scale1[tid]; sbi[tid] = g_bias1[tid]; }
    __syncthreads();
    int lp = tid & 31, chunk = tid >> 5;
    int pg = blockIdx.x * 32 + lp;               // 0 .. CNT-1
    int n = pg / OHWp, p = pg - n * OHWp;
    int c0 = chunk * 32;
    size_t base = ((size_t)n*CC + c0) * OHWp + p;
    unsigned mask = 0;
#pragma unroll 8
    for (int cl = 0; cl < 32; cl++) {
        size_t o = base + (size_t)cl * OHWp;
        float yv = (float)g_y1[o] * ssc[c0+cl] + sbi[c0+cl] + g_mp[o];
        g_x1[o] = yv;
        if (yv > 0.f) mask |= 1u << cl;
    }
    g_bits2u[((size_t)n*8 + chunk) * OHWp + p] = mask;
}

// 1x1 binary conv + fused BN2 stats. Block = (n, oc-tile of 16).
__global__ void k_conv2() {
    int b = blockIdx.x;                 // 512
    int octile = b & 15, n = b >> 4;
    __shared__ unsigned sp[8*OHWp];
    __shared__ unsigned sw[16][8];
    const unsigned* bp = g_bits2u + (size_t)n * 8 * OHWp;
    for (int i = threadIdx.x; i < 8*OHWp; i += 256) sp[i] = bp[i];
    if (threadIdx.x < 128) {
        int oc = threadIdx.x >> 3, k = threadIdx.x & 7;
        sw[oc][k] = ((const unsigned*)g_w2b)[(octile*16 + oc)*8 + k];
    }
    __syncthreads();
    int oc0 = octile * 16;
    short* yp = g_y2 + ((size_t)n*CC + oc0) * OHWp;
    int asum[16], asq[16];
#pragma unroll
    for (int i = 0; i < 16; i++) { asum[i] = 0; asq[i] = 0; }
    for (int p = threadIdx.x; p < OHWp; p += 256) {
        unsigned q[8];
#pragma unroll
        for (int k = 0; k < 8; k++) q[k] = sp[k*OHWp + p];
#pragma unroll
        for (int oc = 0; oc < 16; oc++) {
            int s = 0;
#pragma unroll
            for (int k = 0; k < 8; k++) s += __popc(q[k] ^ sw[oc][k]);
            int val = 256 - 2*s;
            yp[(size_t)oc*OHWp + p] = (short)val;
            asum[oc] += val; asq[oc] += val * val;
        }
    }
    commit_stats16(asum, asq, oc0, g_sum2, g_sq2);
}

// out = bn2(y2) + x1, vectorized 4-wide.
__global__ void k_final(float* __restrict__ out) {
    int i = blockIdx.x * 256 + threadIdx.x;
    if (i >= BB*CC*OHWp/4) return;
    int c = (i / (OHWp/4)) & (CC - 1);
    short4 y = ((const short4*)g_y2)[i];
    float4 x1 = ((const float4*)g_x1)[i];
    float sc = g_scale2[c], bi = g_bias2[c];
    float4 o;
    o.x = (float)y.x * sc + bi + x1.x;
    o.y = (float)y.y * sc + bi + x1.y;
    o.z = (float)y.z * sc + bi + x1.z;
    o.w = (float)y.w * sc + bi + x1.w;
    ((float4*)out)[i] = o;
}

// ---------------- launch ----------------
extern "C" void kernel_launch(void* const* d_in, const int* in_sizes, int n_in,
                              void* d_out, int out_size) {
    const float* x      = (const float*)d_in[0];
    const float* w1     = (const float*)d_in[1];
    const float* w2     = (const float*)d_in[2];
    const float* gamma1 = (const float*)d_in[3];
    const float* beta1  = (const float*)d_in[4];
    const float* gamma2 = (const float*)d_in[5];
    const float* beta2  = (const float*)d_in[6];
    float* out = (float*)d_out;

    k_pack_w<<<(CC*9 + CC*4 + 4*CC + 255)/256, 256>>>(w1, w2);
    k_prolog<<<256, 256>>>(x);
    k_conv1<<<512, 256>>>();
    k_sb<<<1, 256>>>(0, gamma1, beta1);
    k_apply1<<<CNT/32, 256>>>();
    k_conv2<<<512, 256>>>();
    k_sb<<<1, 256>>>(1, gamma2, beta2);
    k_final<<<(BB*CC*OHWp/4 + 255)/256, 256>>>(out);
}

// round 6
// speedup vs baseline: 1.1891x; 1.1891x over previous
#include <cuda_runtime.h>
#include <cfloat>
#include <math.h>

#define BB   32
#define CC   256
#define GG   4
#define CG   64
#define HH   56
#define WW   56
#define OH   28
#define OW   28
#define HWp  (HH*WW)      // 3136
#define OHWp (OH*OW)      // 784
#define CNT  (BB*OHWp)    // 25088
#define BN_EPS 1e-5f

// ---------------- scratch (device globals; no allocation allowed) ----------------
__device__ __align__(32) unsigned long long g_bits1[BB*GG*HWp]; // packed sign(x): [n][g][p]
__device__ unsigned g_bits2u[BB*8*OHWp];                        // packed sign(x1): [n][chunk32][p]
__device__ unsigned long long g_w1b[CC*9];                      // packed sign(w1): [oc][tap]
__device__ unsigned long long g_w2b[CC*4];                      // packed sign(w2): [oc][word]
__device__ short g_y1[BB*CC*OHWp];                              // conv1 raw ints
__device__ short g_y2[BB*CC*OHWp];                              // conv2 raw ints
__device__ float g_x1[BB*CC*OHWp];                              // stage-1 output
__device__ long long g_sum1[CC], g_sq1[CC], g_sum2[CC], g_sq2[CC];

// ---------------- kernels ----------------

// Combined: blocks [0,392) pack sign(x) bit-planes; blocks [392,409) pack weights + zero stats.
__global__ void k_pack(const float* __restrict__ x,
                       const float* __restrict__ w1, const float* __restrict__ w2) {
    if (blockIdx.x < 392) {
        int idx = blockIdx.x * 256 + threadIdx.x;   // (n, g, 4-pixel unit)
        int p4 = idx % (HWp/4);
        int t  = idx / (HWp/4);
        int g = t & 3, n = t >> 2;
        int p = p4 * 4;
        const float* xp = x + ((size_t)(n*CC + g*CG)) * HWp + p;
        unsigned long long m0=0, m1=0, m2=0, m3=0;
#pragma unroll 16
        for (int c = 0; c < CG; c++) {
            float4 v = *(const float4*)(xp + (size_t)c * HWp);
            unsigned long long bt = 1ull << c;
            if (v.x > 0.f) m0 |= bt;
            if (v.y > 0.f) m1 |= bt;
            if (v.z > 0.f) m2 |= bt;
            if (v.w > 0.f) m3 |= bt;
        }
        unsigned long long* o = g_bits1 + ((size_t)(n*GG + g)) * HWp + p;
        ulonglong2 a; a.x = m0; a.y = m1;
        ulonglong2 b2; b2.x = m2; b2.y = m3;
        *(ulonglong2*)o       = a;
        *(ulonglong2*)(o + 2) = b2;
    } else {
        int tid = (blockIdx.x - 392) * 256 + threadIdx.x;
        if (tid < CC * 9) {
            int oc = tid / 9, t = tid % 9;
            unsigned long long m = 0;
            for (int k = 0; k < CG; k++)
                if (w1[(size_t)(oc * CG + k) * 9 + t] > 0.f) m |= 1ull << k;
            g_w1b[tid] = m;
        } else if (tid < CC * 9 + CC * 4) {
            int r = tid - CC * 9;
            int oc = r / 4, j = r % 4;
            unsigned long long m = 0;
            for (int k = 0; k < 64; k++)
                if (w2[(size_t)oc * CC + j * 64 + k] > 0.f) m |= 1ull << k;
            g_w2b[r] = m;
        } else if (tid < CC * 9 + CC * 4 + 4 * CC) {
            int r = tid - (CC * 9 + CC * 4);
            int arr = r >> 8, c = r & 255;
            if      (arr == 0) g_sum1[c] = 0;
            else if (arr == 1) g_sq1[c]  = 0;
            else if (arr == 2) g_sum2[c] = 0;
            else               g_sq2[c]  = 0;
        }
    }
}

__device__ __forceinline__ int warp_red(int v) {
#pragma unroll
    for (int o = 16; o; o >>= 1) v += __shfl_down_sync(0xffffffffu, v, o);
    return v;
}

// Reduce 16 per-thread (sum,sq) pairs across the block, atomically add to globals.
__device__ __forceinline__ void commit_stats16(int* asum, int* asq, int oc0,
                                               long long* gsum, long long* gsq) {
    __shared__ int sred[8][32];
    int lane = threadIdx.x & 31, wid = threadIdx.x >> 5;
#pragma unroll
    for (int oc = 0; oc < 16; oc++) {
        int s = warp_red(asum[oc]);
        int q = warp_red(asq[oc]);
        if (lane == 0) { sred[wid][oc] = s; sred[wid][16 + oc] = q; }
    }
    __syncthreads();
    if (threadIdx.x < 32) {
        int v = 0;
#pragma unroll
        for (int w = 0; w < 8; w++) v += sred[w][threadIdx.x];
        if (threadIdx.x < 16)
            atomicAdd((unsigned long long*)&gsum[oc0 + threadIdx.x], (unsigned long long)(long long)v);
        else
            atomicAdd((unsigned long long*)&gsq[oc0 + threadIdx.x - 16], (unsigned long long)(long long)v);
    }
}

// Grouped 3x3 s2 binary conv + fused BN1 stats. Block = (n, g, oc-tile of 16).
__global__ void k_conv1() {
    int b = blockIdx.x;                 // 512
    int octile = b & 3;
    int g = (b >> 2) & 3;
    int n = b >> 4;
    __shared__ unsigned long long sp[HWp];
    __shared__ unsigned long long sw[16][9];
    const unsigned long long* bp = g_bits1 + (size_t)(n*GG + g) * HWp;
    for (int i = threadIdx.x; i < HWp; i += 256) sp[i] = bp[i];
    if (threadIdx.x < 144) {
        int oc = threadIdx.x / 9, t = threadIdx.x % 9;
        sw[oc][t] = g_w1b[(size_t)(g*CG + octile*16 + oc) * 9 + t];
    }
    __syncthreads();
    int oc0 = g*CG + octile*16;
    short* yp = g_y1 + ((size_t)n*CC + oc0) * OHWp;
    int asum[16], asq[16];
#pragma unroll
    for (int i = 0; i < 16; i++) { asum[i] = 0; asq[i] = 0; }

    for (int p = threadIdx.x; p < OHWp; p += 256) {
        int oh = p / OW, ow = p - oh * OW;
        int ih0 = 2*oh - 1, iw0 = 2*ow - 1;
        unsigned long long a[9];
        if (oh > 0 && ow > 0) {
            const unsigned long long* r = sp + ih0 * WW + iw0;
            a[0]=r[0];    a[1]=r[1];      a[2]=r[2];
            a[3]=r[WW];   a[4]=r[WW+1];   a[5]=r[WW+2];
            a[6]=r[2*WW]; a[7]=r[2*WW+1]; a[8]=r[2*WW+2];
#pragma unroll
            for (int oc = 0; oc < 16; oc++) {
                int s = 0;
#pragma unroll
                for (int t = 0; t < 9; t++) s += __popcll(a[t] ^ sw[oc][t]);
                int val = 576 - 2*s;
                yp[(size_t)oc*OHWp + p] = (short)val;
                asum[oc] += val; asq[oc] += val * val;
            }
        } else {
            bool vld[9]; int nv = 0;
#pragma unroll
            for (int t = 0; t < 9; t++) {
                int ih = ih0 + t/3, iw = iw0 + t%3;
                bool v = ((unsigned)ih < HH) & ((unsigned)iw < WW);
                vld[t] = v;
                a[t] = v ? sp[ih*WW + iw] : 0ull;
                nv += v;
            }
#pragma unroll
            for (int oc = 0; oc < 16; oc++) {
                int s = 0;
#pragma unroll
                for (int t = 0; t < 9; t++) if (vld[t]) s += __popcll(a[t] ^ sw[oc][t]);
                int val = nv*64 - 2*s;
                yp[(size_t)oc*OHWp + p] = (short)val;
                asum[oc] += val; asq[oc] += val * val;
            }
        }
    }
    commit_stats16(asum, asq, oc0, g_sum1, g_sq1);
}

// Fused: per-block BN1 coefficients from stats, then x1 = bn1(y1) + maxpool3x3s2(x),
// pack sign(x1). Warp = 32-channel chunk, lanes = pixels; maxpool via float2 + shfl.
__global__ void k_apply1(const float* __restrict__ x,
                         const float* __restrict__ gamma1, const float* __restrict__ beta1) {
    __shared__ float ssc[CC], sbi[CC];
    int tid = threadIdx.x;
    if (tid < CC) {
        float mu  = (float)g_sum1[tid] * (1.f/CNT);
        float var = (float)g_sq1[tid] * (1.f/CNT) - mu * mu;
        float sc  = gamma1[tid] * rsqrtf(var + BN_EPS);
        ssc[tid] = sc;
        sbi[tid] = beta1[tid] - mu * sc;
    }
    __syncthreads();
    int lp = tid & 31, chunk = tid >> 5;
    int pg = blockIdx.x * 32 + lp;               // 0 .. CNT-1
    int n = pg / OHWp, p = pg - n * OHWp;
    int oh = p / OW, ow = p - oh * OW;
    int c0 = chunk * 32;
    int ih0 = 2*oh - 1;
    size_t ybase = ((size_t)n*CC + c0) * OHWp + p;
    const float* xb = x + ((size_t)n*CC + c0) * HWp + 2*ow;
    unsigned mask = 0;
#pragma unroll 4
    for (int cl = 0; cl < 32; cl++) {
        const float* xc = xb + (size_t)cl * HWp;
        float m = -FLT_MAX;
#pragma unroll
        for (int r = 0; r < 3; r++) {
            int ih = ih0 + r;
            bool vr = (ih >= 0);                 // ih <= 55 always
            float2 f;
            if (vr) f = *(const float2*)(xc + ih * WW);
            else { f.x = -FLT_MAX; f.y = -FLT_MAX; }
            float left = __shfl_up_sync(0xffffffffu, f.y, 1);
            float hm = fmaxf(f.x, f.y);
            if (ow > 0) {
                if (lp == 0) left = vr ? xc[ih * WW - 1] : -FLT_MAX;
                hm = fmaxf(hm, left);
            }
            m = fmaxf(m, hm);
        }
        float yv = (float)g_y1[ybase + (size_t)cl*OHWp] * ssc[c0+cl] + sbi[c0+cl] + m;
        g_x1[ybase + (size_t)cl*OHWp] = yv;
        if (yv > 0.f) mask |= 1u << cl;
    }
    g_bits2u[((size_t)n*8 + chunk) * OHWp + p] = mask;   // coalesced: fixed chunk per warp
}

// 1x1 binary conv + fused BN2 stats. Block = (n, oc-tile of 16); bits staged in smem planes.
__global__ void k_conv2() {
    int b = blockIdx.x;                 // 512
    int octile = b & 15, n = b >> 4;
    __shared__ unsigned sp[8*OHWp];
    __shared__ unsigned sw[16][8];
    const unsigned* bp = g_bits2u + (size_t)n * 8 * OHWp;
    for (int i = threadIdx.x; i < 8*OHWp; i += 256) sp[i] = bp[i];
    if (threadIdx.x < 128) {
        int oc = threadIdx.x >> 3, k = threadIdx.x & 7;
        sw[oc][k] = ((const unsigned*)g_w2b)[(octile*16 + oc)*8 + k];
    }
    __syncthreads();
    int oc0 = octile * 16;
    short* yp = g_y2 + ((size_t)n*CC + oc0) * OHWp;
    int asum[16], asq[16];
#pragma unroll
    for (int i = 0; i < 16; i++) { asum[i] = 0; asq[i] = 0; }
    for (int p = threadIdx.x; p < OHWp; p += 256) {
        unsigned q[8];
#pragma unroll
        for (int k = 0; k < 8; k++) q[k] = sp[k*OHWp + p];
#pragma unroll
        for (int oc = 0; oc < 16; oc++) {
            int s = 0;
#pragma unroll
            for (int k = 0; k < 8; k++) s += __popc(q[k] ^ sw[oc][k]);
            int val = 256 - 2*s;
            yp[(size_t)oc*OHWp + p] = (short)val;
            asum[oc] += val; asq[oc] += val * val;
        }
    }
    commit_stats16(asum, asq, oc0, g_sum2, g_sq2);
}

// out = bn2(y2) + x1, float4; BN2 coefficients computed per-thread (stat arrays are L1-hot).
__global__ void k_final(float* __restrict__ out,
                        const float* __restrict__ gamma2, const float* __restrict__ beta2) {
    int i = blockIdx.x * 256 + threadIdx.x;
    if (i >= BB*CC*OHWp/4) return;
    int c = (i / (OHWp/4)) & (CC - 1);
    float mu  = (float)g_sum2[c] * (1.f/CNT);
    float var = (float)g_sq2[c] * (1.f/CNT) - mu * mu;
    float sc  = __ldg(&gamma2[c]) * rsqrtf(var + BN_EPS);
    float bi  = __ldg(&beta2[c]) - mu * sc;
    short4 y = ((const short4*)g_y2)[i];
    float4 x1 = ((const float4*)g_x1)[i];
    float4 o;
    o.x = (float)y.x * sc + bi + x1.x;
    o.y = (float)y.y * sc + bi + x1.y;
    o.z = (float)y.z * sc + bi + x1.z;
    o.w = (float)y.w * sc + bi + x1.w;
    ((float4*)out)[i] = o;
}

// ---------------- launch ----------------
extern "C" void kernel_launch(void* const* d_in, const int* in_sizes, int n_in,
                              void* d_out, int out_size) {
    const float* x      = (const float*)d_in[0];
    const float* w1     = (const float*)d_in[1];
    const float* w2     = (const float*)d_in[2];
    const float* gamma1 = (const float*)d_in[3];
    const float* beta1  = (const float*)d_in[4];
    const float* gamma2 = (const float*)d_in[5];
    const float* beta2  = (const float*)d_in[6];
    float* out = (float*)d_out;

    k_pack<<<409, 256>>>(x, w1, w2);
    k_conv1<<<512, 256>>>();
    k_apply1<<<CNT/32, 256>>>(x, gamma1, beta1);
    k_conv2<<<512, 256>>>();
    k_final<<<(BB*CC*OHWp/4 + 255)/256, 256>>>(out, gamma2, beta2);
}